// round 1
// baseline (speedup 1.0000x reference)
#include <cuda_runtime.h>
#include <cuda_bf16.h>

// ---------------- problem constants ----------------
#define S       2048
#define DIM     4096
#define NH      32
#define NKV     8
#define HD      128
#define QKV_N   6144            // 4096 (Q) + 1024 (K) + 1024 (V)
#define K_OFF   4096
#define V_OFF   5120

// scratch (static device globals are the sanctioned scratch mechanism)
__device__ float g_qkv[S * QKV_N];      // 48 MB: [s][Qheads*128 | Kheads*128 | Vheads*128]
__device__ float g_attn[S * DIM];       // 32 MB: attention output [s][h*128+d]

// ---------------- GEMM: C[m, coff+n0+n] = sum_k A[m,k] * B[n,k] ----------------
// A: [M,K] row-major, B: [N,K] row-major (rows = output features), C row stride ldc.
#define BM 64
#define BN 64
#define BK 16

__global__ __launch_bounds__(256) void gemm_nt(
    const float* __restrict__ A, const float* __restrict__ B,
    float* __restrict__ C, int M, int N, int K, int ldc, int coff)
{
    __shared__ float As[BK][BM];   // k-major staging
    __shared__ float Bs[BK][BN];

    const int tid = threadIdx.x;
    const int m0 = blockIdx.y * BM;
    const int n0 = blockIdx.x * BN;

    const int lr = tid >> 2;          // 0..63 row within tile
    const int lk = (tid & 3) * 4;     // k-quad
    const int ty = tid >> 4;          // 0..15
    const int tx = tid & 15;          // 0..15

    const float* Ap = A + (size_t)(m0 + lr) * K + lk;
    const float* Bp = B + (size_t)(n0 + lr) * K + lk;

    float acc[4][4];
    #pragma unroll
    for (int i = 0; i < 4; i++)
        #pragma unroll
        for (int j = 0; j < 4; j++) acc[i][j] = 0.f;

    for (int k0 = 0; k0 < K; k0 += BK) {
        float4 av = *(const float4*)(Ap + k0);
        float4 bv = *(const float4*)(Bp + k0);
        __syncthreads();
        As[lk + 0][lr] = av.x; As[lk + 1][lr] = av.y;
        As[lk + 2][lr] = av.z; As[lk + 3][lr] = av.w;
        Bs[lk + 0][lr] = bv.x; Bs[lk + 1][lr] = bv.y;
        Bs[lk + 2][lr] = bv.z; Bs[lk + 3][lr] = bv.w;
        __syncthreads();

        #pragma unroll
        for (int kk = 0; kk < BK; kk++) {
            float4 a = *(const float4*)&As[kk][ty * 4];
            float4 b = *(const float4*)&Bs[kk][tx * 4];
            acc[0][0] += a.x * b.x; acc[0][1] += a.x * b.y; acc[0][2] += a.x * b.z; acc[0][3] += a.x * b.w;
            acc[1][0] += a.y * b.x; acc[1][1] += a.y * b.y; acc[1][2] += a.y * b.z; acc[1][3] += a.y * b.w;
            acc[2][0] += a.z * b.x; acc[2][1] += a.z * b.y; acc[2][2] += a.z * b.z; acc[2][3] += a.z * b.w;
            acc[3][0] += a.w * b.x; acc[3][1] += a.w * b.y; acc[3][2] += a.w * b.z; acc[3][3] += a.w * b.w;
        }
    }

    #pragma unroll
    for (int i = 0; i < 4; i++) {
        float4 v = make_float4(acc[i][0], acc[i][1], acc[i][2], acc[i][3]);
        *(float4*)&C[(size_t)(m0 + ty * 4 + i) * ldc + coff + n0 + tx * 4] = v;
    }
}

// ---------------- RoPE on Q and K heads in-place ----------------
__global__ void rope_kernel(float* __restrict__ qkv,
                            const float* __restrict__ cs,
                            const float* __restrict__ sn)
{
    int p = blockIdx.x * blockDim.x + threadIdx.x;     // S * 40 heads * 64 pairs
    if (p >= S * 40 * 64) return;
    int i = p & 63;
    int h = (p >> 6) % 40;
    int s = p / (40 * 64);
    int col = (h < NH) ? (h * HD + 2 * i) : (K_OFF + (h - NH) * HD + 2 * i);
    float* t = qkv + (size_t)s * QKV_N + col;
    float re = t[0], im = t[1];
    float c = cs[s * 64 + i], si = sn[s * 64 + i];
    t[0] = re * c - im * si;
    t[1] = re * si + im * c;
}

// ---------------- Flash attention (fp32, causal, GQA 4:1) ----------------
// grid: (S/64 q-tiles, NH heads), block 256 threads.
#define LDK 132                 // padded row stride for Q/K/V tiles (bank spread)
#define LDS_ 65                 // padded row stride for score tile

__global__ __launch_bounds__(256) void attn_kernel(
    const float* __restrict__ qkv, float* __restrict__ out)
{
    extern __shared__ float sm[];
    float* Qs = sm;                          // 64*132
    float* Ks = Qs + 64 * LDK;               // 64*132
    float* Vs = Ks + 64 * LDK;               // 64*132
    float* Ss = Vs + 64 * LDK;               // 64*65
    float* row_m = Ss + 64 * LDS_;           // 64
    float* row_l = row_m + 64;               // 64
    float* row_c = row_l + 64;               // 64

    const int tid = threadIdx.x;
    const int qt = blockIdx.x;
    const int h  = blockIdx.y;
    const int kvh = h >> 2;
    const int q_s0 = qt * 64;

    // load Q tile (64 x 128)
    #pragma unroll
    for (int i = 0; i < 8; i++) {
        int fid = tid + i * 256;             // 0..2047 float4 ids
        int r = fid >> 5;
        int c4 = fid & 31;
        *(float4*)&Qs[r * LDK + c4 * 4] =
            *(const float4*)&qkv[(size_t)(q_s0 + r) * QKV_N + h * HD + c4 * 4];
    }
    if (tid < 64) { row_m[tid] = -1e30f; row_l[tid] = 0.f; }

    const int rb = (tid >> 4) * 4;           // 4 consecutive rows
    const int cx = tid & 15;                 // strided column base

    float acc[4][8];
    #pragma unroll
    for (int i = 0; i < 4; i++)
        #pragma unroll
        for (int j = 0; j < 8; j++) acc[i][j] = 0.f;

    const float scale = 0.08838834764831845f;   // 1/sqrt(128)

    for (int kt = 0; kt <= qt; kt++) {
        __syncthreads();    // previous iteration done with Ks/Vs/Ss
        const int k_s0 = kt * 64;
        #pragma unroll
        for (int i = 0; i < 8; i++) {
            int fid = tid + i * 256;
            int r = fid >> 5;
            int c4 = fid & 31;
            *(float4*)&Ks[r * LDK + c4 * 4] =
                *(const float4*)&qkv[(size_t)(k_s0 + r) * QKV_N + K_OFF + kvh * HD + c4 * 4];
            *(float4*)&Vs[r * LDK + c4 * 4] =
                *(const float4*)&qkv[(size_t)(k_s0 + r) * QKV_N + V_OFF + kvh * HD + c4 * 4];
        }
        __syncthreads();

        // scores: 4 rows x 4 strided cols per thread
        float sc[4][4];
        #pragma unroll
        for (int i = 0; i < 4; i++)
            #pragma unroll
            for (int j = 0; j < 4; j++) sc[i][j] = 0.f;

        for (int kk = 0; kk < HD; kk += 4) {
            float4 qv[4], kv[4];
            #pragma unroll
            for (int i = 0; i < 4; i++) qv[i] = *(const float4*)&Qs[(rb + i) * LDK + kk];
            #pragma unroll
            for (int j = 0; j < 4; j++) kv[j] = *(const float4*)&Ks[(cx + 16 * j) * LDK + kk];
            #pragma unroll
            for (int i = 0; i < 4; i++)
                #pragma unroll
                for (int j = 0; j < 4; j++)
                    sc[i][j] += qv[i].x * kv[j].x + qv[i].y * kv[j].y
                              + qv[i].z * kv[j].z + qv[i].w * kv[j].w;
        }

        const bool diag = (kt == qt);
        #pragma unroll
        for (int i = 0; i < 4; i++)
            #pragma unroll
            for (int j = 0; j < 4; j++) {
                int c = cx + 16 * j;
                float s = sc[i][j] * scale;
                if (diag && c > rb + i) s = -1e9f;
                Ss[(rb + i) * LDS_ + c] = s;
            }
        __syncthreads();

        // online softmax, one owner thread per row
        if (tid < 64) {
            int r = tid;
            float mo = row_m[r], mx = mo;
            #pragma unroll
            for (int c = 0; c < 64; c++) mx = fmaxf(mx, Ss[r * LDS_ + c]);
            float corr = __expf(mo - mx);
            float sum = 0.f;
            #pragma unroll
            for (int c = 0; c < 64; c++) {
                float p = __expf(Ss[r * LDS_ + c] - mx);
                Ss[r * LDS_ + c] = p;
                sum += p;
            }
            row_l[r] = row_l[r] * corr + sum;
            row_m[r] = mx;
            row_c[r] = corr;
        }
        __syncthreads();

        // PV accumulate: rescale then add P @ V
        float cr[4];
        #pragma unroll
        for (int i = 0; i < 4; i++) cr[i] = row_c[rb + i];
        #pragma unroll
        for (int i = 0; i < 4; i++)
            #pragma unroll
            for (int j = 0; j < 8; j++) acc[i][j] *= cr[i];

        for (int c = 0; c < 64; c++) {
            float p[4], v[8];
            #pragma unroll
            for (int i = 0; i < 4; i++) p[i] = Ss[(rb + i) * LDS_ + c];
            #pragma unroll
            for (int j = 0; j < 8; j++) v[j] = Vs[c * LDK + cx + 16 * j];
            #pragma unroll
            for (int i = 0; i < 4; i++)
                #pragma unroll
                for (int j = 0; j < 8; j++) acc[i][j] += p[i] * v[j];
        }
    }

    // normalize and write out: out[s][h*128 + d]
    float li[4];
    #pragma unroll
    for (int i = 0; i < 4; i++) li[i] = 1.f / row_l[rb + i];
    #pragma unroll
    for (int i = 0; i < 4; i++)
        #pragma unroll
        for (int j = 0; j < 8; j++)
            out[(size_t)(q_s0 + rb + i) * DIM + h * HD + cx + 16 * j] = acc[i][j] * li[i];
}

// ---------------- launch ----------------
extern "C" void kernel_launch(void* const* d_in, const int* in_sizes, int n_in,
                              void* d_out, int out_size)
{
    const float* x  = (const float*)d_in[0];
    const float* fc = (const float*)d_in[1];
    const float* fs = (const float*)d_in[2];
    // d_in[3] mask, d_in[4] positions: window==S => pure causal, handled in-kernel
    const float* wq = (const float*)d_in[5];
    const float* wk = (const float*)d_in[6];
    const float* wv = (const float*)d_in[7];
    const float* wo = (const float*)d_in[8];
    float* out = (float*)d_out;

    float* qkv = nullptr;
    float* att = nullptr;
    cudaGetSymbolAddress((void**)&qkv, g_qkv);
    cudaGetSymbolAddress((void**)&att, g_attn);

    const int smem_attn = (3 * 64 * LDK + 64 * LDS_ + 3 * 64) * sizeof(float);
    cudaFuncSetAttribute(attn_kernel, cudaFuncAttributeMaxDynamicSharedMemorySize, smem_attn);

    dim3 blk(256);
    // QKV projections into packed buffer
    gemm_nt<<<dim3(DIM / BN, S / BM), blk>>>(x, wq, qkv, S, DIM,  DIM, QKV_N, 0);
    gemm_nt<<<dim3(1024 / BN, S / BM), blk>>>(x, wk, qkv, S, 1024, DIM, QKV_N, K_OFF);
    gemm_nt<<<dim3(1024 / BN, S / BM), blk>>>(x, wv, qkv, S, 1024, DIM, QKV_N, V_OFF);

    // RoPE on Q + K
    rope_kernel<<<(S * 40 * 64 + 255) / 256, blk>>>(qkv, fc, fs);

    // attention
    attn_kernel<<<dim3(S / 64, NH), blk, smem_attn>>>(qkv, att);

    // output projection
    gemm_nt<<<dim3(DIM / BN, S / BM), blk>>>(att, wo, out, S, DIM, DIM, DIM, 0);
}

// round 4
// speedup vs baseline: 2.3351x; 2.3351x over previous
#include <cuda_runtime.h>
#include <cuda_bf16.h>
#include <cstdint>

// ---------------- problem constants ----------------
#define S       2048
#define DIM     4096
#define NH      32
#define HD      128
#define QKV_N   6144
#define K_OFF   4096
#define V_OFF   5120

// ---------------- scratch (device globals) ----------------
__device__ float g_qkv[S * QKV_N];
__device__ float g_attn[S * DIM];
__device__ __nv_bfloat16 g_xh[S * DIM],  g_xl[S * DIM];
__device__ __nv_bfloat16 g_wh[QKV_N * DIM], g_wl[QKV_N * DIM];   // packed wq|wk|wv
__device__ __nv_bfloat16 g_oh[DIM * DIM], g_ol[DIM * DIM];       // wo
__device__ __nv_bfloat16 g_ah[S * DIM],  g_al[S * DIM];          // attention out split

// ---------------- helpers ----------------
__device__ __forceinline__ uint32_t smem_u32(const void* p) {
    uint32_t a;
    asm("{ .reg .u64 t; cvta.to.shared.u64 t, %1; cvt.u32.u64 %0, t; }" : "=r"(a) : "l"(p));
    return a;
}
__device__ __forceinline__ void cp16(uint32_t dst, const void* src) {
    asm volatile("cp.async.cg.shared.global [%0], [%1], 16;" :: "r"(dst), "l"(src));
}
__device__ __forceinline__ void cp_commit() {
    asm volatile("cp.async.commit_group;");
}
template <int N>
__device__ __forceinline__ void cp_wait() {
    asm volatile("cp.async.wait_group %0;" :: "n"(N));
}
__device__ __forceinline__ void ldm_x4(uint32_t* r, uint32_t addr) {
    asm volatile("ldmatrix.sync.aligned.m8n8.x4.shared.b16 {%0,%1,%2,%3}, [%4];"
                 : "=r"(r[0]), "=r"(r[1]), "=r"(r[2]), "=r"(r[3]) : "r"(addr));
}
__device__ __forceinline__ void mma16816(float* c, const uint32_t* a, uint32_t b0, uint32_t b1) {
    asm volatile(
        "mma.sync.aligned.m16n8k16.row.col.f32.bf16.bf16.f32 "
        "{%0,%1,%2,%3}, {%4,%5,%6,%7}, {%8,%9}, {%0,%1,%2,%3};"
        : "+f"(c[0]), "+f"(c[1]), "+f"(c[2]), "+f"(c[3])
        : "r"(a[0]), "r"(a[1]), "r"(a[2]), "r"(a[3]), "r"(b0), "r"(b1));
}

// ---------------- split fp32 -> (bf16 hi, bf16 lo) ----------------
__global__ void split_kernel(const float* __restrict__ src,
                             __nv_bfloat16* __restrict__ hi,
                             __nv_bfloat16* __restrict__ lo, int n4)
{
    int i = blockIdx.x * blockDim.x + threadIdx.x;
    if (i >= n4) return;
    float4 v = ((const float4*)src)[i];
    __nv_bfloat16 h0 = __float2bfloat16(v.x), h1 = __float2bfloat16(v.y);
    __nv_bfloat16 h2 = __float2bfloat16(v.z), h3 = __float2bfloat16(v.w);
    __nv_bfloat16 l0 = __float2bfloat16(v.x - __bfloat162float(h0));
    __nv_bfloat16 l1 = __float2bfloat16(v.y - __bfloat162float(h1));
    __nv_bfloat16 l2 = __float2bfloat16(v.z - __bfloat162float(h2));
    __nv_bfloat16 l3 = __float2bfloat16(v.w - __bfloat162float(h3));
    __nv_bfloat162 hv0 = {h0, h1}, hv1 = {h2, h3};
    __nv_bfloat162 lv0 = {l0, l1}, lv1 = {l2, l3};
    ((__nv_bfloat162*)hi)[2 * i]     = hv0;
    ((__nv_bfloat162*)hi)[2 * i + 1] = hv1;
    ((__nv_bfloat162*)lo)[2 * i]     = lv0;
    ((__nv_bfloat162*)lo)[2 * i + 1] = lv1;
}

// ---------------- bf16x3 GEMM via mma.sync ----------------
// C[m,n] = sum_k A[m,k]*B[n,k], fp32-accurate via Ah*Bh + Ah*Bl + Al*Bh.
// CTA tile 128x128, BK=64. 8 warps: warp = 32(m) x 64(n).
// Smem: 4 tiles (Ah,Al,Bh,Bl) of 128 rows x 128B, XOR-swizzled, double buffered.
#define TILE_B  (128 * 128)          // bytes per operand tile
#define BUF_B   (4 * TILE_B)         // 64 KB per stage
#define GEMM_SMEM (2 * BUF_B)        // 128 KB

__global__ __launch_bounds__(256, 1) void gemm_bf16x3(
    const __nv_bfloat16* __restrict__ Ah, const __nv_bfloat16* __restrict__ Al,
    const __nv_bfloat16* __restrict__ Bh, const __nv_bfloat16* __restrict__ Bl,
    float* __restrict__ C, int K, int ldc)
{
    extern __shared__ __align__(1024) char smc[];
    const uint32_t sbase = smem_u32(smc);

    const int tid  = threadIdx.x;
    const int lane = tid & 31;
    const int wid  = tid >> 5;
    const int wm   = wid & 3;          // 0..3 -> m offset 32*wm
    const int wn   = wid >> 2;         // 0..1 -> n offset 64*wn
    const int m0 = blockIdx.x * 128;
    const int n0 = blockIdx.y * 128;

    // global load mapping: 1024 16B-lines per tile, 4 per thread
    const int gr = tid >> 3;           // row 0..31 (+32*i)
    const int gc = tid & 7;            // 16B col 0..7

    // ldmatrix lane mapping
    const int grp = lane >> 3;         // matrix 0..3
    const int rin = lane & 7;

    float acc[2][8][4];
    #pragma unroll
    for (int i = 0; i < 2; i++)
        #pragma unroll
        for (int j = 0; j < 8; j++)
            #pragma unroll
            for (int q = 0; q < 4; q++) acc[i][j][q] = 0.f;

    const int nk = K >> 6;

    // ---- chunk loader ----
    auto load_chunk = [&](int buf, int it) {
        const int k0 = it << 6;                           // bf16 elements
        const uint32_t sb = sbase + buf * BUF_B;
        #pragma unroll
        for (int i = 0; i < 4; i++) {
            int r = gr + i * 32;
            uint32_t so = (uint32_t)(r * 128) + ((uint32_t)(gc ^ (r & 7)) << 4);
            size_t goff = ((size_t)r * K + k0 + gc * 8);  // elements
            cp16(sb + so,              Ah + (size_t)m0 * K + goff);
            cp16(sb + TILE_B + so,     Al + (size_t)m0 * K + goff);
            cp16(sb + 2 * TILE_B + so, Bh + (size_t)n0 * K + goff);
            cp16(sb + 3 * TILE_B + so, Bl + (size_t)n0 * K + goff);
        }
        cp_commit();
    };

    load_chunk(0, 0);

    for (int it = 0; it < nk; it++) {
        const int buf = it & 1;
        if (it + 1 < nk) { load_chunk(buf ^ 1, it + 1); cp_wait<1>(); }
        else             { cp_wait<0>(); }
        __syncthreads();

        const uint32_t sb = sbase + buf * BUF_B;
        #pragma unroll
        for (int kc = 0; kc < 4; kc++) {
            const int ccol = kc * 2 + (grp >> 1);         // 16B col for this lane

            // A fragments (hi & lo), 2 m16 tiles each
            uint32_t ah[2][4], al[2][4];
            #pragma unroll
            for (int am = 0; am < 2; am++) {
                int row = wm * 32 + am * 16 + rin + (grp & 1) * 8;
                uint32_t so = (uint32_t)(row * 128) + ((uint32_t)(ccol ^ (row & 7)) << 4);
                ldm_x4(ah[am], sb + so);
                ldm_x4(al[am], sb + TILE_B + so);
            }

            // B hi fragments: 4 n16 tiles -> 8 n8 atoms
            uint32_t bq[4][4];
            #pragma unroll
            for (int bt = 0; bt < 4; bt++) {
                int row = wn * 64 + bt * 16 + rin + (grp & 1) * 8;
                uint32_t so = (uint32_t)(row * 128) + ((uint32_t)(ccol ^ (row & 7)) << 4);
                ldm_x4(bq[bt], sb + 2 * TILE_B + so);
            }
            #pragma unroll
            for (int bt = 0; bt < 4; bt++) {
                #pragma unroll
                for (int am = 0; am < 2; am++) {
                    mma16816(acc[am][2 * bt],     ah[am], bq[bt][0], bq[bt][2]);
                    mma16816(acc[am][2 * bt + 1], ah[am], bq[bt][1], bq[bt][3]);
                    mma16816(acc[am][2 * bt],     al[am], bq[bt][0], bq[bt][2]);
                    mma16816(acc[am][2 * bt + 1], al[am], bq[bt][1], bq[bt][3]);
                }
            }

            // B lo fragments (reuse regs)
            #pragma unroll
            for (int bt = 0; bt < 4; bt++) {
                int row = wn * 64 + bt * 16 + rin + (grp & 1) * 8;
                uint32_t so = (uint32_t)(row * 128) + ((uint32_t)(ccol ^ (row & 7)) << 4);
                ldm_x4(bq[bt], sb + 3 * TILE_B + so);
            }
            #pragma unroll
            for (int bt = 0; bt < 4; bt++) {
                #pragma unroll
                for (int am = 0; am < 2; am++) {
                    mma16816(acc[am][2 * bt],     ah[am], bq[bt][0], bq[bt][2]);
                    mma16816(acc[am][2 * bt + 1], ah[am], bq[bt][1], bq[bt][3]);
                }
            }
        }
        __syncthreads();
    }

    // epilogue: direct fp32 stores (float2 per atom-half)
    #pragma unroll
    for (int am = 0; am < 2; am++) {
        int row = m0 + wm * 32 + am * 16 + (lane >> 2);
        #pragma unroll
        for (int bn = 0; bn < 8; bn++) {
            int col = n0 + wn * 64 + bn * 8 + (lane & 3) * 2;
            *(float2*)&C[(size_t)row * ldc + col]       = make_float2(acc[am][bn][0], acc[am][bn][1]);
            *(float2*)&C[(size_t)(row + 8) * ldc + col] = make_float2(acc[am][bn][2], acc[am][bn][3]);
        }
    }
}

// ---------------- RoPE on Q and K heads in-place ----------------
__global__ void rope_kernel(float* __restrict__ qkv,
                            const float* __restrict__ cs,
                            const float* __restrict__ sn)
{
    int p = blockIdx.x * blockDim.x + threadIdx.x;
    if (p >= S * 40 * 64) return;
    int i = p & 63;
    int h = (p >> 6) % 40;
    int s = p / (40 * 64);
    int col = (h < NH) ? (h * HD + 2 * i) : (K_OFF + (h - NH) * HD + 2 * i);
    float* t = qkv + (size_t)s * QKV_N + col;
    float re = t[0], im = t[1];
    float c = cs[s * 64 + i], si = sn[s * 64 + i];
    t[0] = re * c - im * si;
    t[1] = re * si + im * c;
}

// ---------------- Flash attention (fp32, causal, GQA 4:1) ----------------
#define LDK 132
#define LDS_ 65

__global__ __launch_bounds__(256) void attn_kernel(
    const float* __restrict__ qkv, float* __restrict__ out)
{
    extern __shared__ float sm[];
    float* Qs = sm;
    float* Ks = Qs + 64 * LDK;
    float* Vs = Ks + 64 * LDK;
    float* Ss = Vs + 64 * LDK;
    float* row_m = Ss + 64 * LDS_;
    float* row_l = row_m + 64;
    float* row_c = row_l + 64;

    const int tid = threadIdx.x;
    const int qt = blockIdx.x;
    const int h  = blockIdx.y;
    const int kvh = h >> 2;
    const int q_s0 = qt * 64;

    #pragma unroll
    for (int i = 0; i < 8; i++) {
        int fid = tid + i * 256;
        int r = fid >> 5;
        int c4 = fid & 31;
        *(float4*)&Qs[r * LDK + c4 * 4] =
            *(const float4*)&qkv[(size_t)(q_s0 + r) * QKV_N + h * HD + c4 * 4];
    }
    if (tid < 64) { row_m[tid] = -1e30f; row_l[tid] = 0.f; }

    const int rb = (tid >> 4) * 4;
    const int cx = tid & 15;

    float acc[4][8];
    #pragma unroll
    for (int i = 0; i < 4; i++)
        #pragma unroll
        for (int j = 0; j < 8; j++) acc[i][j] = 0.f;

    const float scale = 0.08838834764831845f;

    for (int kt = 0; kt <= qt; kt++) {
        __syncthreads();
        const int k_s0 = kt * 64;
        #pragma unroll
        for (int i = 0; i < 8; i++) {
            int fid = tid + i * 256;
            int r = fid >> 5;
            int c4 = fid & 31;
            *(float4*)&Ks[r * LDK + c4 * 4] =
                *(const float4*)&qkv[(size_t)(k_s0 + r) * QKV_N + K_OFF + kvh * HD + c4 * 4];
            *(float4*)&Vs[r * LDK + c4 * 4] =
                *(const float4*)&qkv[(size_t)(k_s0 + r) * QKV_N + V_OFF + kvh * HD + c4 * 4];
        }
        __syncthreads();

        float sc[4][4];
        #pragma unroll
        for (int i = 0; i < 4; i++)
            #pragma unroll
            for (int j = 0; j < 4; j++) sc[i][j] = 0.f;

        for (int kk = 0; kk < HD; kk += 4) {
            float4 qv[4], kv[4];
            #pragma unroll
            for (int i = 0; i < 4; i++) qv[i] = *(const float4*)&Qs[(rb + i) * LDK + kk];
            #pragma unroll
            for (int j = 0; j < 4; j++) kv[j] = *(const float4*)&Ks[(cx + 16 * j) * LDK + kk];
            #pragma unroll
            for (int i = 0; i < 4; i++)
                #pragma unroll
                for (int j = 0; j < 4; j++)
                    sc[i][j] += qv[i].x * kv[j].x + qv[i].y * kv[j].y
                              + qv[i].z * kv[j].z + qv[i].w * kv[j].w;
        }

        const bool diag = (kt == qt);
        #pragma unroll
        for (int i = 0; i < 4; i++)
            #pragma unroll
            for (int j = 0; j < 4; j++) {
                int c = cx + 16 * j;
                float s = sc[i][j] * scale;
                if (diag && c > rb + i) s = -1e9f;
                Ss[(rb + i) * LDS_ + c] = s;
            }
        __syncthreads();

        if (tid < 64) {
            int r = tid;
            float mo = row_m[r], mx = mo;
            #pragma unroll
            for (int c = 0; c < 64; c++) mx = fmaxf(mx, Ss[r * LDS_ + c]);
            float corr = __expf(mo - mx);
            float sum = 0.f;
            #pragma unroll
            for (int c = 0; c < 64; c++) {
                float p = __expf(Ss[r * LDS_ + c] - mx);
                Ss[r * LDS_ + c] = p;
                sum += p;
            }
            row_l[r] = row_l[r] * corr + sum;
            row_m[r] = mx;
            row_c[r] = corr;
        }
        __syncthreads();

        float cr[4];
        #pragma unroll
        for (int i = 0; i < 4; i++) cr[i] = row_c[rb + i];
        #pragma unroll
        for (int i = 0; i < 4; i++)
            #pragma unroll
            for (int j = 0; j < 8; j++) acc[i][j] *= cr[i];

        for (int c = 0; c < 64; c++) {
            float p[4], v[8];
            #pragma unroll
            for (int i = 0; i < 4; i++) p[i] = Ss[(rb + i) * LDS_ + c];
            #pragma unroll
            for (int j = 0; j < 8; j++) v[j] = Vs[c * LDK + cx + 16 * j];
            #pragma unroll
            for (int i = 0; i < 4; i++)
                #pragma unroll
                for (int j = 0; j < 8; j++) acc[i][j] += p[i] * v[j];
        }
    }

    float li[4];
    #pragma unroll
    for (int i = 0; i < 4; i++) li[i] = 1.f / row_l[rb + i];
    #pragma unroll
    for (int i = 0; i < 4; i++)
        #pragma unroll
        for (int j = 0; j < 8; j++)
            out[(size_t)(q_s0 + rb + i) * DIM + h * HD + cx + 16 * j] = acc[i][j] * li[i];
}

// ---------------- launch ----------------
extern "C" void kernel_launch(void* const* d_in, const int* in_sizes, int n_in,
                              void* d_out, int out_size)
{
    const float* x  = (const float*)d_in[0];
    const float* fc = (const float*)d_in[1];
    const float* fs = (const float*)d_in[2];
    const float* wq = (const float*)d_in[5];
    const float* wk = (const float*)d_in[6];
    const float* wv = (const float*)d_in[7];
    const float* wo = (const float*)d_in[8];
    float* out = (float*)d_out;

    float *qkv, *att;
    __nv_bfloat16 *xh, *xl, *wh, *wl, *oh, *ol, *ah, *al;
    cudaGetSymbolAddress((void**)&qkv, g_qkv);
    cudaGetSymbolAddress((void**)&att, g_attn);
    cudaGetSymbolAddress((void**)&xh, g_xh);  cudaGetSymbolAddress((void**)&xl, g_xl);
    cudaGetSymbolAddress((void**)&wh, g_wh);  cudaGetSymbolAddress((void**)&wl, g_wl);
    cudaGetSymbolAddress((void**)&oh, g_oh);  cudaGetSymbolAddress((void**)&ol, g_ol);
    cudaGetSymbolAddress((void**)&ah, g_ah);  cudaGetSymbolAddress((void**)&al, g_al);

    cudaFuncSetAttribute(gemm_bf16x3, cudaFuncAttributeMaxDynamicSharedMemorySize, GEMM_SMEM);
    const int smem_attn = (3 * 64 * LDK + 64 * LDS_ + 3 * 64) * sizeof(float);
    cudaFuncSetAttribute(attn_kernel, cudaFuncAttributeMaxDynamicSharedMemorySize, smem_attn);

    dim3 blk(256);
    int n4x = S * DIM / 4;
    split_kernel<<<(n4x + 255) / 256, blk>>>(x, xh, xl, n4x);
    int n4q = DIM * DIM / 4;
    split_kernel<<<(n4q + 255) / 256, blk>>>(wq, wh, wl, n4q);
    int n4k = 1024 * DIM / 4;
    split_kernel<<<(n4k + 255) / 256, blk>>>(wk, wh + (size_t)4096 * DIM, wl + (size_t)4096 * DIM, n4k);
    split_kernel<<<(n4k + 255) / 256, blk>>>(wv, wh + (size_t)5120 * DIM, wl + (size_t)5120 * DIM, n4k);
    split_kernel<<<(n4q + 255) / 256, blk>>>(wo, oh, ol, n4q);

    // QKV projection: [2048 x 6144] (grid.x = m for L2 reuse of B)
    gemm_bf16x3<<<dim3(S / 128, QKV_N / 128), blk, GEMM_SMEM>>>(xh, xl, wh, wl, qkv, DIM, QKV_N);

    // RoPE
    rope_kernel<<<(S * 40 * 64 + 255) / 256, blk>>>(qkv, fc, fs);

    // attention
    attn_kernel<<<dim3(S / 64, NH), blk, smem_attn>>>(qkv, att);

    // split attention output, then output projection
    split_kernel<<<(n4x + 255) / 256, blk>>>(att, ah, al, n4x);
    gemm_bf16x3<<<dim3(S / 128, DIM / 128), blk, GEMM_SMEM>>>(ah, al, oh, ol, out, DIM, DIM);
}

// round 5
// speedup vs baseline: 3.5444x; 1.5179x over previous
#include <cuda_runtime.h>
#include <cuda_bf16.h>
#include <cstdint>

// ---------------- problem constants ----------------
#define S       2048
#define DIM     4096
#define NH      32
#define HD      128
#define QKV_N   6144
#define K_OFF   4096
#define V_OFF   5120

// ---------------- scratch (device globals) ----------------
__device__ float g_qkv[S * QKV_N];
__device__ __nv_bfloat16 g_qh[S * QKV_N], g_ql[S * QKV_N];       // rope'd qkv hi/lo
__device__ __nv_bfloat16 g_xh[S * DIM],  g_xl[S * DIM];
__device__ __nv_bfloat16 g_wh[QKV_N * DIM], g_wl[QKV_N * DIM];   // packed wq|wk|wv
__device__ __nv_bfloat16 g_oh[DIM * DIM], g_ol[DIM * DIM];       // wo
__device__ __nv_bfloat16 g_ah[S * DIM],  g_al[S * DIM];          // attention out split

// ---------------- helpers ----------------
__device__ __forceinline__ uint32_t smem_u32(const void* p) {
    uint32_t a;
    asm("{ .reg .u64 t; cvta.to.shared.u64 t, %1; cvt.u32.u64 %0, t; }" : "=r"(a) : "l"(p));
    return a;
}
__device__ __forceinline__ void cp16(uint32_t dst, const void* src) {
    asm volatile("cp.async.cg.shared.global [%0], [%1], 16;" :: "r"(dst), "l"(src));
}
__device__ __forceinline__ void cp_commit() {
    asm volatile("cp.async.commit_group;");
}
template <int N>
__device__ __forceinline__ void cp_wait() {
    asm volatile("cp.async.wait_group %0;" :: "n"(N));
}
__device__ __forceinline__ void ldm_x4(uint32_t* r, uint32_t addr) {
    asm volatile("ldmatrix.sync.aligned.m8n8.x4.shared.b16 {%0,%1,%2,%3}, [%4];"
                 : "=r"(r[0]), "=r"(r[1]), "=r"(r[2]), "=r"(r[3]) : "r"(addr));
}
__device__ __forceinline__ void ldm_x4t(uint32_t* r, uint32_t addr) {
    asm volatile("ldmatrix.sync.aligned.m8n8.x4.trans.shared.b16 {%0,%1,%2,%3}, [%4];"
                 : "=r"(r[0]), "=r"(r[1]), "=r"(r[2]), "=r"(r[3]) : "r"(addr));
}
__device__ __forceinline__ void mma16816(float* c, const uint32_t* a, uint32_t b0, uint32_t b1) {
    asm volatile(
        "mma.sync.aligned.m16n8k16.row.col.f32.bf16.bf16.f32 "
        "{%0,%1,%2,%3}, {%4,%5,%6,%7}, {%8,%9}, {%0,%1,%2,%3};"
        : "+f"(c[0]), "+f"(c[1]), "+f"(c[2]), "+f"(c[3])
        : "r"(a[0]), "r"(a[1]), "r"(a[2]), "r"(a[3]), "r"(b0), "r"(b1));
}
__device__ __forceinline__ void pack_hl(float x, float y, uint32_t& h, uint32_t& l) {
    __nv_bfloat162 hb = __floats2bfloat162_rn(x, y);
    float hx = __bfloat162float(hb.x), hy = __bfloat162float(hb.y);
    __nv_bfloat162 lb = __floats2bfloat162_rn(x - hx, y - hy);
    h = *reinterpret_cast<uint32_t*>(&hb);
    l = *reinterpret_cast<uint32_t*>(&lb);
}

// ---------------- split fp32 -> (bf16 hi, bf16 lo) ----------------
__global__ void split_kernel(const float* __restrict__ src,
                             __nv_bfloat16* __restrict__ hi,
                             __nv_bfloat16* __restrict__ lo, int n4)
{
    int i = blockIdx.x * blockDim.x + threadIdx.x;
    if (i >= n4) return;
    float4 v = ((const float4*)src)[i];
    __nv_bfloat16 h0 = __float2bfloat16(v.x), h1 = __float2bfloat16(v.y);
    __nv_bfloat16 h2 = __float2bfloat16(v.z), h3 = __float2bfloat16(v.w);
    __nv_bfloat16 l0 = __float2bfloat16(v.x - __bfloat162float(h0));
    __nv_bfloat16 l1 = __float2bfloat16(v.y - __bfloat162float(h1));
    __nv_bfloat16 l2 = __float2bfloat16(v.z - __bfloat162float(h2));
    __nv_bfloat16 l3 = __float2bfloat16(v.w - __bfloat162float(h3));
    __nv_bfloat162 hv0 = {h0, h1}, hv1 = {h2, h3};
    __nv_bfloat162 lv0 = {l0, l1}, lv1 = {l2, l3};
    ((__nv_bfloat162*)hi)[2 * i]     = hv0;
    ((__nv_bfloat162*)hi)[2 * i + 1] = hv1;
    ((__nv_bfloat162*)lo)[2 * i]     = lv0;
    ((__nv_bfloat162*)lo)[2 * i + 1] = lv1;
}

// ---------------- fused RoPE + split of qkv ----------------
__global__ void rope_split(const float* __restrict__ qkv,
                           const float* __restrict__ cs, const float* __restrict__ sn,
                           __nv_bfloat16* __restrict__ qh, __nv_bfloat16* __restrict__ ql)
{
    int p = blockIdx.x * blockDim.x + threadIdx.x;      // S * 3072 pairs
    if (p >= S * 3072) return;
    int s = p / 3072, cp = p % 3072;
    int col = cp * 2;
    const float* src = qkv + (size_t)s * QKV_N + col;
    float f0 = src[0], f1 = src[1];
    if (col < V_OFF) {                                   // Q or K: apply rope
        int i = cp & 63;
        float c = cs[s * 64 + i], si = sn[s * 64 + i];
        float r0 = f0 * c - f1 * si, r1 = f0 * si + f1 * c;
        f0 = r0; f1 = r1;
    }
    __nv_bfloat162 hb = __floats2bfloat162_rn(f0, f1);
    __nv_bfloat162 lb = __floats2bfloat162_rn(f0 - __bfloat162float(hb.x),
                                              f1 - __bfloat162float(hb.y));
    *(__nv_bfloat162*)&qh[(size_t)s * QKV_N + col] = hb;
    *(__nv_bfloat162*)&ql[(size_t)s * QKV_N + col] = lb;
}

// ---------------- bf16x3 GEMM via mma.sync (unchanged from R4) ----------------
#define TILE_B  (128 * 128)
#define BUF_B   (4 * TILE_B)
#define GEMM_SMEM (2 * BUF_B)

__global__ __launch_bounds__(256, 1) void gemm_bf16x3(
    const __nv_bfloat16* __restrict__ Ah, const __nv_bfloat16* __restrict__ Al,
    const __nv_bfloat16* __restrict__ Bh, const __nv_bfloat16* __restrict__ Bl,
    float* __restrict__ C, int K, int ldc)
{
    extern __shared__ __align__(1024) char smc[];
    const uint32_t sbase = smem_u32(smc);

    const int tid  = threadIdx.x;
    const int lane = tid & 31;
    const int wid  = tid >> 5;
    const int wm   = wid & 3;
    const int wn   = wid >> 2;
    const int m0 = blockIdx.x * 128;
    const int n0 = blockIdx.y * 128;

    const int gr = tid >> 3;
    const int gc = tid & 7;
    const int grp = lane >> 3;
    const int rin = lane & 7;

    float acc[2][8][4];
    #pragma unroll
    for (int i = 0; i < 2; i++)
        #pragma unroll
        for (int j = 0; j < 8; j++)
            #pragma unroll
            for (int q = 0; q < 4; q++) acc[i][j][q] = 0.f;

    const int nk = K >> 6;

    auto load_chunk = [&](int buf, int it) {
        const int k0 = it << 6;
        const uint32_t sb = sbase + buf * BUF_B;
        #pragma unroll
        for (int i = 0; i < 4; i++) {
            int r = gr + i * 32;
            uint32_t so = (uint32_t)(r * 128) + ((uint32_t)(gc ^ (r & 7)) << 4);
            size_t goff = ((size_t)r * K + k0 + gc * 8);
            cp16(sb + so,              Ah + (size_t)m0 * K + goff);
            cp16(sb + TILE_B + so,     Al + (size_t)m0 * K + goff);
            cp16(sb + 2 * TILE_B + so, Bh + (size_t)n0 * K + goff);
            cp16(sb + 3 * TILE_B + so, Bl + (size_t)n0 * K + goff);
        }
        cp_commit();
    };

    load_chunk(0, 0);

    for (int it = 0; it < nk; it++) {
        const int buf = it & 1;
        if (it + 1 < nk) { load_chunk(buf ^ 1, it + 1); cp_wait<1>(); }
        else             { cp_wait<0>(); }
        __syncthreads();

        const uint32_t sb = sbase + buf * BUF_B;
        #pragma unroll
        for (int kc = 0; kc < 4; kc++) {
            const int ccol = kc * 2 + (grp >> 1);

            uint32_t ah[2][4], al[2][4];
            #pragma unroll
            for (int am = 0; am < 2; am++) {
                int row = wm * 32 + am * 16 + rin + (grp & 1) * 8;
                uint32_t so = (uint32_t)(row * 128) + ((uint32_t)(ccol ^ (row & 7)) << 4);
                ldm_x4(ah[am], sb + so);
                ldm_x4(al[am], sb + TILE_B + so);
            }

            uint32_t bq[4][4];
            #pragma unroll
            for (int bt = 0; bt < 4; bt++) {
                int row = wn * 64 + bt * 16 + rin + (grp & 1) * 8;
                uint32_t so = (uint32_t)(row * 128) + ((uint32_t)(ccol ^ (row & 7)) << 4);
                ldm_x4(bq[bt], sb + 2 * TILE_B + so);
            }
            #pragma unroll
            for (int bt = 0; bt < 4; bt++) {
                #pragma unroll
                for (int am = 0; am < 2; am++) {
                    mma16816(acc[am][2 * bt],     ah[am], bq[bt][0], bq[bt][2]);
                    mma16816(acc[am][2 * bt + 1], ah[am], bq[bt][1], bq[bt][3]);
                    mma16816(acc[am][2 * bt],     al[am], bq[bt][0], bq[bt][2]);
                    mma16816(acc[am][2 * bt + 1], al[am], bq[bt][1], bq[bt][3]);
                }
            }

            #pragma unroll
            for (int bt = 0; bt < 4; bt++) {
                int row = wn * 64 + bt * 16 + rin + (grp & 1) * 8;
                uint32_t so = (uint32_t)(row * 128) + ((uint32_t)(ccol ^ (row & 7)) << 4);
                ldm_x4(bq[bt], sb + 3 * TILE_B + so);
            }
            #pragma unroll
            for (int bt = 0; bt < 4; bt++) {
                #pragma unroll
                for (int am = 0; am < 2; am++) {
                    mma16816(acc[am][2 * bt],     ah[am], bq[bt][0], bq[bt][2]);
                    mma16816(acc[am][2 * bt + 1], ah[am], bq[bt][1], bq[bt][3]);
                }
            }
        }
        __syncthreads();
    }

    #pragma unroll
    for (int am = 0; am < 2; am++) {
        int row = m0 + wm * 32 + am * 16 + (lane >> 2);
        #pragma unroll
        for (int bn = 0; bn < 8; bn++) {
            int col = n0 + wn * 64 + bn * 8 + (lane & 3) * 2;
            *(float2*)&C[(size_t)row * ldc + col]       = make_float2(acc[am][bn][0], acc[am][bn][1]);
            *(float2*)&C[(size_t)(row + 8) * ldc + col] = make_float2(acc[am][bn][2], acc[am][bn][3]);
        }
    }
}

// ---------------- tensor-core flash attention (bf16x3, causal, GQA 4:1) ----------------
// q-tile 128, key-tile 64, 8 warps x 16 q-rows. Output written as bf16 hi/lo.
#define ATT_SMEM (192 * 1024)

__global__ __launch_bounds__(256, 1) void attn_mma(
    const __nv_bfloat16* __restrict__ qh_g, const __nv_bfloat16* __restrict__ ql_g,
    __nv_bfloat16* __restrict__ ah_g, __nv_bfloat16* __restrict__ al_g)
{
    extern __shared__ __align__(1024) char smb[];
    const uint32_t sb = smem_u32(smb);
    const uint32_t sQh = sb, sQl = sb + 32 * 1024;
    // stage st: base = sb + 64K + st*64K; Kh +0, Kl +16K, Vh +32K, Vl +48K

    const int tid = threadIdx.x, lane = tid & 31, wid = tid >> 5;
    const int qt = (int)gridDim.x - 1 - (int)blockIdx.x;   // heavy tiles first
    const int h = blockIdx.y, kvh = h >> 2;
    const int q0 = qt * 128;
    const int wq = wid * 16;

    // ---- Q tile load (hi/lo), cp.async group 0 ----
    #pragma unroll
    for (int i = 0; i < 8; i++) {
        int ch = tid + i * 256;                 // 0..2047
        int row = ch >> 4, c16 = ch & 15;
        uint32_t so = (uint32_t)(row * 256) + (uint32_t)((c16 ^ (row & 7)) << 4);
        size_t g = (size_t)(q0 + row) * QKV_N + h * HD + c16 * 8;
        cp16(sQh + so, qh_g + g);
        cp16(sQl + so, ql_g + g);
    }
    cp_commit();

    const int ktmax = 2 * qt + 1;
    auto load_kv = [&](int kt) {
        const uint32_t st = sb + 64 * 1024 + (uint32_t)(kt & 1) * 64 * 1024;
        const int k0 = kt * 64;
        #pragma unroll
        for (int i = 0; i < 4; i++) {
            int ch = tid + i * 256;             // 0..1023
            int row = ch >> 4, c16 = ch & 15;
            uint32_t so = (uint32_t)(row * 256) + (uint32_t)((c16 ^ (row & 7)) << 4);
            size_t kb = (size_t)(k0 + row) * QKV_N + kvh * HD + c16 * 8;
            cp16(st + so,             qh_g + kb + K_OFF);
            cp16(st + 16 * 1024 + so, ql_g + kb + K_OFF);
            cp16(st + 32 * 1024 + so, qh_g + kb + V_OFF);
            cp16(st + 48 * 1024 + so, ql_g + kb + V_OFF);
        }
        cp_commit();
    };
    load_kv(0);

    float oacc[16][4];
    #pragma unroll
    for (int a = 0; a < 16; a++)
        #pragma unroll
        for (int q = 0; q < 4; q++) oacc[a][q] = 0.f;
    float m0 = -1e30f, m1 = -1e30f, l0 = 0.f, l1 = 0.f;
    const float kscale = 0.08838834764831845f * 1.44269504088896f;   // scale*log2(e)

    const int rin = lane & 7, grp = lane >> 3;
    const int arow = wq + rin + (grp & 1) * 8;
    const int r0 = lane >> 2;                  // accumulator row within m16

    for (int kt = 0; kt <= ktmax; kt++) {
        if (kt < ktmax) { load_kv(kt + 1); cp_wait<1>(); }
        else            { cp_wait<0>(); }
        __syncthreads();

        const bool skip = (kt * 64) > (q0 + wq + 15);    // warp tile fully masked
        if (!skip) {
            const uint32_t st = sb + 64 * 1024 + (uint32_t)(kt & 1) * 64 * 1024;

            // ---- scores: QK^T bf16x3 ----
            float sc[8][4];
            #pragma unroll
            for (int a = 0; a < 8; a++)
                #pragma unroll
                for (int q = 0; q < 4; q++) sc[a][q] = 0.f;

            #pragma unroll
            for (int k16 = 0; k16 < 8; k16++) {
                const int c16 = k16 * 2 + (grp >> 1);
                uint32_t aoff = (uint32_t)(arow * 256) + (uint32_t)((c16 ^ (arow & 7)) << 4);
                uint32_t aqh[4], aql[4];
                ldm_x4(aqh, sQh + aoff);
                ldm_x4(aql, sQl + aoff);
                #pragma unroll
                for (int bt = 0; bt < 4; bt++) {
                    int brow = bt * 16 + rin + (grp & 1) * 8;
                    uint32_t boff = (uint32_t)(brow * 256) + (uint32_t)((c16 ^ (brow & 7)) << 4);
                    uint32_t bh[4], bl[4];
                    ldm_x4(bh, st + boff);
                    ldm_x4(bl, st + 16 * 1024 + boff);
                    mma16816(sc[2 * bt],     aqh, bh[0], bh[2]);
                    mma16816(sc[2 * bt + 1], aqh, bh[1], bh[3]);
                    mma16816(sc[2 * bt],     aqh, bl[0], bl[2]);
                    mma16816(sc[2 * bt + 1], aqh, bl[1], bl[3]);
                    mma16816(sc[2 * bt],     aql, bh[0], bh[2]);
                    mma16816(sc[2 * bt + 1], aql, bh[1], bh[3]);
                }
            }

            // ---- causal mask ----
            if (kt * 64 + 63 > q0 + wq) {
                int qr0 = q0 + wq + r0, qr1 = qr0 + 8;
                int cb = kt * 64 + 2 * (lane & 3);
                #pragma unroll
                for (int a = 0; a < 8; a++) {
                    int c0 = cb + a * 8, c1 = c0 + 1;
                    if (c0 > qr0) sc[a][0] = -1e30f;
                    if (c1 > qr0) sc[a][1] = -1e30f;
                    if (c0 > qr1) sc[a][2] = -1e30f;
                    if (c1 > qr1) sc[a][3] = -1e30f;
                }
            }

            // ---- online softmax (register, quad-reduced) ----
            float mx0 = -1e30f, mx1 = -1e30f;
            #pragma unroll
            for (int a = 0; a < 8; a++) {
                mx0 = fmaxf(mx0, fmaxf(sc[a][0], sc[a][1]));
                mx1 = fmaxf(mx1, fmaxf(sc[a][2], sc[a][3]));
            }
            mx0 = fmaxf(mx0, __shfl_xor_sync(0xffffffffu, mx0, 1));
            mx0 = fmaxf(mx0, __shfl_xor_sync(0xffffffffu, mx0, 2));
            mx1 = fmaxf(mx1, __shfl_xor_sync(0xffffffffu, mx1, 1));
            mx1 = fmaxf(mx1, __shfl_xor_sync(0xffffffffu, mx1, 2));
            float nm0 = fmaxf(m0, mx0), nm1 = fmaxf(m1, mx1);
            float corr0 = exp2f((m0 - nm0) * kscale);
            float corr1 = exp2f((m1 - nm1) * kscale);
            float s0 = 0.f, s1 = 0.f;
            #pragma unroll
            for (int a = 0; a < 8; a++) {
                sc[a][0] = exp2f((sc[a][0] - nm0) * kscale);
                sc[a][1] = exp2f((sc[a][1] - nm0) * kscale);
                sc[a][2] = exp2f((sc[a][2] - nm1) * kscale);
                sc[a][3] = exp2f((sc[a][3] - nm1) * kscale);
                s0 += sc[a][0] + sc[a][1];
                s1 += sc[a][2] + sc[a][3];
            }
            s0 += __shfl_xor_sync(0xffffffffu, s0, 1);
            s0 += __shfl_xor_sync(0xffffffffu, s0, 2);
            s1 += __shfl_xor_sync(0xffffffffu, s1, 1);
            s1 += __shfl_xor_sync(0xffffffffu, s1, 2);
            l0 = l0 * corr0 + s0;
            l1 = l1 * corr1 + s1;
            m0 = nm0; m1 = nm1;
            #pragma unroll
            for (int a = 0; a < 16; a++) {
                oacc[a][0] *= corr0; oacc[a][1] *= corr0;
                oacc[a][2] *= corr1; oacc[a][3] *= corr1;
            }

            // ---- PV: bf16x3 with register P ----
            #pragma unroll
            for (int t = 0; t < 4; t++) {
                uint32_t ph[4], pl[4];
                pack_hl(sc[2 * t][0],     sc[2 * t][1],     ph[0], pl[0]);
                pack_hl(sc[2 * t][2],     sc[2 * t][3],     ph[1], pl[1]);
                pack_hl(sc[2 * t + 1][0], sc[2 * t + 1][1], ph[2], pl[2]);
                pack_hl(sc[2 * t + 1][2], sc[2 * t + 1][3], ph[3], pl[3]);
                #pragma unroll
                for (int d = 0; d < 8; d++) {
                    int vrow = t * 16 + (grp & 1) * 8 + rin;
                    int c16 = d * 2 + (grp >> 1);
                    uint32_t voff = (uint32_t)(vrow * 256) + (uint32_t)((c16 ^ (vrow & 7)) << 4);
                    uint32_t vh[4], vl[4];
                    ldm_x4t(vh, st + 32 * 1024 + voff);
                    ldm_x4t(vl, st + 48 * 1024 + voff);
                    mma16816(oacc[2 * d],     ph, vh[0], vh[1]);
                    mma16816(oacc[2 * d + 1], ph, vh[2], vh[3]);
                    mma16816(oacc[2 * d],     ph, vl[0], vl[1]);
                    mma16816(oacc[2 * d + 1], ph, vl[2], vl[3]);
                    mma16816(oacc[2 * d],     pl, vh[0], vh[1]);
                    mma16816(oacc[2 * d + 1], pl, vh[2], vh[3]);
                }
            }
        }
        __syncthreads();
    }

    // ---- epilogue: normalize, write bf16 hi/lo ----
    float inv0 = 1.f / l0, inv1 = 1.f / l1;
    int gr0 = q0 + wq + r0, gr1 = gr0 + 8;
    #pragma unroll
    for (int a = 0; a < 16; a++) {
        int d0 = a * 8 + 2 * (lane & 3);
        float v0 = oacc[a][0] * inv0, v1 = oacc[a][1] * inv0;
        float w0 = oacc[a][2] * inv1, w1 = oacc[a][3] * inv1;
        uint32_t hb, lb;
        pack_hl(v0, v1, hb, lb);
        *(uint32_t*)&ah_g[(size_t)gr0 * DIM + h * HD + d0] = hb;
        *(uint32_t*)&al_g[(size_t)gr0 * DIM + h * HD + d0] = lb;
        pack_hl(w0, w1, hb, lb);
        *(uint32_t*)&ah_g[(size_t)gr1 * DIM + h * HD + d0] = hb;
        *(uint32_t*)&al_g[(size_t)gr1 * DIM + h * HD + d0] = lb;
    }
}

// ---------------- launch ----------------
extern "C" void kernel_launch(void* const* d_in, const int* in_sizes, int n_in,
                              void* d_out, int out_size)
{
    const float* x  = (const float*)d_in[0];
    const float* fc = (const float*)d_in[1];
    const float* fs = (const float*)d_in[2];
    const float* wq = (const float*)d_in[5];
    const float* wk = (const float*)d_in[6];
    const float* wv = (const float*)d_in[7];
    const float* wo = (const float*)d_in[8];
    float* out = (float*)d_out;

    float *qkv;
    __nv_bfloat16 *qh, *ql, *xh, *xl, *wh, *wl, *oh, *ol, *ah, *al;
    cudaGetSymbolAddress((void**)&qkv, g_qkv);
    cudaGetSymbolAddress((void**)&qh, g_qh);  cudaGetSymbolAddress((void**)&ql, g_ql);
    cudaGetSymbolAddress((void**)&xh, g_xh);  cudaGetSymbolAddress((void**)&xl, g_xl);
    cudaGetSymbolAddress((void**)&wh, g_wh);  cudaGetSymbolAddress((void**)&wl, g_wl);
    cudaGetSymbolAddress((void**)&oh, g_oh);  cudaGetSymbolAddress((void**)&ol, g_ol);
    cudaGetSymbolAddress((void**)&ah, g_ah);  cudaGetSymbolAddress((void**)&al, g_al);

    cudaFuncSetAttribute(gemm_bf16x3, cudaFuncAttributeMaxDynamicSharedMemorySize, GEMM_SMEM);
    cudaFuncSetAttribute(attn_mma, cudaFuncAttributeMaxDynamicSharedMemorySize, ATT_SMEM);

    dim3 blk(256);
    int n4x = S * DIM / 4;
    split_kernel<<<(n4x + 255) / 256, blk>>>(x, xh, xl, n4x);
    int n4q = DIM * DIM / 4;
    split_kernel<<<(n4q + 255) / 256, blk>>>(wq, wh, wl, n4q);
    int n4k = 1024 * DIM / 4;
    split_kernel<<<(n4k + 255) / 256, blk>>>(wk, wh + (size_t)4096 * DIM, wl + (size_t)4096 * DIM, n4k);
    split_kernel<<<(n4k + 255) / 256, blk>>>(wv, wh + (size_t)5120 * DIM, wl + (size_t)5120 * DIM, n4k);
    split_kernel<<<(n4q + 255) / 256, blk>>>(wo, oh, ol, n4q);

    // QKV projection (fp32 out)
    gemm_bf16x3<<<dim3(S / 128, QKV_N / 128), blk, GEMM_SMEM>>>(xh, xl, wh, wl, qkv, DIM, QKV_N);

    // fused RoPE + hi/lo split of qkv
    rope_split<<<(S * 3072 + 255) / 256, blk>>>(qkv, fc, fs, qh, ql);

    // tensor-core attention -> bf16 hi/lo output
    attn_mma<<<dim3(S / 128, NH), blk, ATT_SMEM>>>(qh, ql, ah, al);

    // output projection
    gemm_bf16x3<<<dim3(S / 128, DIM / 128), blk, GEMM_SMEM>>>(ah, al, oh, ol, out, DIM, DIM);
}

// round 6
// speedup vs baseline: 3.5889x; 1.0125x over previous
#include <cuda_runtime.h>
#include <cuda_bf16.h>
#include <cstdint>

// ---------------- problem constants ----------------
#define S       2048
#define DIM     4096
#define NH      32
#define HD      128
#define QKV_N   6144
#define K_OFF   4096
#define V_OFF   5120

// ---------------- scratch (device globals) ----------------
__device__ __nv_bfloat16 g_qh[S * QKV_N], g_ql[S * QKV_N];       // rope'd qkv hi/lo
__device__ __nv_bfloat16 g_xh[S * DIM],  g_xl[S * DIM];
__device__ __nv_bfloat16 g_wh[QKV_N * DIM], g_wl[QKV_N * DIM];   // packed wq|wk|wv
__device__ __nv_bfloat16 g_oh[DIM * DIM], g_ol[DIM * DIM];       // wo
__device__ __nv_bfloat16 g_ah[S * DIM],  g_al[S * DIM];          // attention out split

// ---------------- helpers ----------------
__device__ __forceinline__ uint32_t smem_u32(const void* p) {
    uint32_t a;
    asm("{ .reg .u64 t; cvta.to.shared.u64 t, %1; cvt.u32.u64 %0, t; }" : "=r"(a) : "l"(p));
    return a;
}
__device__ __forceinline__ void cp16(uint32_t dst, const void* src) {
    asm volatile("cp.async.cg.shared.global [%0], [%1], 16;" :: "r"(dst), "l"(src));
}
__device__ __forceinline__ void cp_commit() {
    asm volatile("cp.async.commit_group;");
}
template <int N>
__device__ __forceinline__ void cp_wait() {
    asm volatile("cp.async.wait_group %0;" :: "n"(N));
}
__device__ __forceinline__ void ldm_x4(uint32_t* r, uint32_t addr) {
    asm volatile("ldmatrix.sync.aligned.m8n8.x4.shared.b16 {%0,%1,%2,%3}, [%4];"
                 : "=r"(r[0]), "=r"(r[1]), "=r"(r[2]), "=r"(r[3]) : "r"(addr));
}
__device__ __forceinline__ void ldm_x4t(uint32_t* r, uint32_t addr) {
    asm volatile("ldmatrix.sync.aligned.m8n8.x4.trans.shared.b16 {%0,%1,%2,%3}, [%4];"
                 : "=r"(r[0]), "=r"(r[1]), "=r"(r[2]), "=r"(r[3]) : "r"(addr));
}
__device__ __forceinline__ void mma16816(float* c, const uint32_t* a, uint32_t b0, uint32_t b1) {
    asm volatile(
        "mma.sync.aligned.m16n8k16.row.col.f32.bf16.bf16.f32 "
        "{%0,%1,%2,%3}, {%4,%5,%6,%7}, {%8,%9}, {%0,%1,%2,%3};"
        : "+f"(c[0]), "+f"(c[1]), "+f"(c[2]), "+f"(c[3])
        : "r"(a[0]), "r"(a[1]), "r"(a[2]), "r"(a[3]), "r"(b0), "r"(b1));
}
__device__ __forceinline__ void pack_hl(float x, float y, uint32_t& h, uint32_t& l) {
    __nv_bfloat162 hb = __floats2bfloat162_rn(x, y);
    float hx = __bfloat162float(hb.x), hy = __bfloat162float(hb.y);
    __nv_bfloat162 lb = __floats2bfloat162_rn(x - hx, y - hy);
    h = *reinterpret_cast<uint32_t*>(&hb);
    l = *reinterpret_cast<uint32_t*>(&lb);
}

// ---------------- split fp32 -> (bf16 hi, bf16 lo) ----------------
__global__ void split_kernel(const float* __restrict__ src,
                             __nv_bfloat16* __restrict__ hi,
                             __nv_bfloat16* __restrict__ lo, int n4)
{
    int i = blockIdx.x * blockDim.x + threadIdx.x;
    if (i >= n4) return;
    float4 v = ((const float4*)src)[i];
    __nv_bfloat16 h0 = __float2bfloat16(v.x), h1 = __float2bfloat16(v.y);
    __nv_bfloat16 h2 = __float2bfloat16(v.z), h3 = __float2bfloat16(v.w);
    __nv_bfloat16 l0 = __float2bfloat16(v.x - __bfloat162float(h0));
    __nv_bfloat16 l1 = __float2bfloat16(v.y - __bfloat162float(h1));
    __nv_bfloat16 l2 = __float2bfloat16(v.z - __bfloat162float(h2));
    __nv_bfloat16 l3 = __float2bfloat16(v.w - __bfloat162float(h3));
    __nv_bfloat162 hv0 = {h0, h1}, hv1 = {h2, h3};
    __nv_bfloat162 lv0 = {l0, l1}, lv1 = {l2, l3};
    ((__nv_bfloat162*)hi)[2 * i]     = hv0;
    ((__nv_bfloat162*)hi)[2 * i + 1] = hv1;
    ((__nv_bfloat162*)lo)[2 * i]     = lv0;
    ((__nv_bfloat162*)lo)[2 * i + 1] = lv1;
}

// ---------------- bf16x3 GEMM via mma.sync, CTA 128x256, warp 64x64 ----------------
// C[m,n] = sum_k A[m,k]*B[n,k] via Ah*Bh + Ah*Bl + Al*Bh.
// mode 0: write fp32 C (ldc stride)
// mode 1: QKV epilogue -> RoPE (cols < V_OFF) + hi/lo bf16 split into qh/ql
#define A_HI 0
#define A_LO (16 * 1024)
#define B_HI (32 * 1024)
#define B_LO (64 * 1024)
#define STG_B (96 * 1024)
#define GEMM_SMEM (2 * STG_B)

__global__ __launch_bounds__(256, 1) void gemm_bf16x3(
    const __nv_bfloat16* __restrict__ Ah, const __nv_bfloat16* __restrict__ Al,
    const __nv_bfloat16* __restrict__ Bh, const __nv_bfloat16* __restrict__ Bl,
    float* __restrict__ C, int K, int ldc, int mode,
    const float* __restrict__ cs, const float* __restrict__ sn,
    __nv_bfloat16* __restrict__ Oh, __nv_bfloat16* __restrict__ Ol)
{
    extern __shared__ __align__(1024) char smc[];
    const uint32_t sbase = smem_u32(smc);

    const int tid  = threadIdx.x;
    const int lane = tid & 31;
    const int wid  = tid >> 5;
    const int wm   = wid & 1;           // 2 m-halves of 64
    const int wn   = wid >> 1;          // 4 n-quarters of 64
    const int m0 = blockIdx.x * 128;
    const int n0 = blockIdx.y * 256;

    const int grp = lane >> 3;
    const int rin = lane & 7;

    float acc[4][8][4];
    #pragma unroll
    for (int i = 0; i < 4; i++)
        #pragma unroll
        for (int j = 0; j < 8; j++)
            #pragma unroll
            for (int q = 0; q < 4; q++) acc[i][j][q] = 0.f;

    const int nk = K >> 6;

    auto load_chunk = [&](int buf, int it) {
        const int k0 = it << 6;
        const uint32_t sb = sbase + buf * STG_B;
        #pragma unroll
        for (int i = 0; i < 4; i++) {                    // A: 1024 lines
            int id = tid + i * 256;
            int row = id >> 3, c16 = id & 7;
            uint32_t so = (uint32_t)(row * 128) + ((uint32_t)(c16 ^ (row & 7)) << 4);
            size_t g = (size_t)(m0 + row) * K + k0 + c16 * 8;
            cp16(sb + A_HI + so, Ah + g);
            cp16(sb + A_LO + so, Al + g);
        }
        #pragma unroll
        for (int i = 0; i < 8; i++) {                    // B: 2048 lines
            int id = tid + i * 256;
            int row = id >> 3, c16 = id & 7;
            uint32_t so = (uint32_t)(row * 128) + ((uint32_t)(c16 ^ (row & 7)) << 4);
            size_t g = (size_t)(n0 + row) * K + k0 + c16 * 8;
            cp16(sb + B_HI + so, Bh + g);
            cp16(sb + B_LO + so, Bl + g);
        }
        cp_commit();
    };

    load_chunk(0, 0);

    for (int it = 0; it < nk; it++) {
        const int buf = it & 1;
        if (it + 1 < nk) { load_chunk(buf ^ 1, it + 1); cp_wait<1>(); }
        else             { cp_wait<0>(); }
        __syncthreads();

        const uint32_t sA = sbase + buf * STG_B;
        const uint32_t sB = sA + B_HI;
        #pragma unroll
        for (int kc = 0; kc < 4; kc++) {
            const int c16 = kc * 2 + (grp >> 1);

            uint32_t ah[4][4], al[4][4];
            #pragma unroll
            for (int am = 0; am < 4; am++) {
                int row = wm * 64 + am * 16 + rin + (grp & 1) * 8;
                uint32_t so = (uint32_t)(row * 128) + ((uint32_t)(c16 ^ (row & 7)) << 4);
                ldm_x4(ah[am], sA + so);
                ldm_x4(al[am], sA + A_LO + so);
            }

            #pragma unroll
            for (int bt = 0; bt < 4; bt++) {
                int row = wn * 64 + bt * 16 + rin + (grp & 1) * 8;
                uint32_t so = (uint32_t)(row * 128) + ((uint32_t)(c16 ^ (row & 7)) << 4);
                uint32_t bh[4], bl[4];
                ldm_x4(bh, sB + so);
                ldm_x4(bl, sB + (B_LO - B_HI) + so);
                #pragma unroll
                for (int am = 0; am < 4; am++) {
                    mma16816(acc[am][2 * bt],     ah[am], bh[0], bh[2]);
                    mma16816(acc[am][2 * bt + 1], ah[am], bh[1], bh[3]);
                    mma16816(acc[am][2 * bt],     al[am], bh[0], bh[2]);
                    mma16816(acc[am][2 * bt + 1], al[am], bh[1], bh[3]);
                    mma16816(acc[am][2 * bt],     ah[am], bl[0], bl[2]);
                    mma16816(acc[am][2 * bt + 1], ah[am], bl[1], bl[3]);
                }
            }
        }
        __syncthreads();
    }

    // ---- epilogue ----
    if (mode == 0) {
        #pragma unroll
        for (int am = 0; am < 4; am++) {
            int row = m0 + wm * 64 + am * 16 + (lane >> 2);
            #pragma unroll
            for (int bn = 0; bn < 8; bn++) {
                int col = n0 + wn * 64 + bn * 8 + (lane & 3) * 2;
                *(float2*)&C[(size_t)row * ldc + col]       = make_float2(acc[am][bn][0], acc[am][bn][1]);
                *(float2*)&C[(size_t)(row + 8) * ldc + col] = make_float2(acc[am][bn][2], acc[am][bn][3]);
            }
        }
    } else {
        // RoPE on cols < V_OFF, then bf16 hi/lo split -> Oh/Ol. cols (col,col+1) are a rope pair.
        #pragma unroll
        for (int am = 0; am < 4; am++) {
            int row = m0 + wm * 64 + am * 16 + (lane >> 2);
            #pragma unroll
            for (int bn = 0; bn < 8; bn++) {
                int col = n0 + wn * 64 + bn * 8 + (lane & 3) * 2;
                int i = (col & (HD - 1)) >> 1;
                bool rope = col < V_OFF;
                #pragma unroll
                for (int half = 0; half < 2; half++) {
                    int r = row + half * 8;
                    float v0 = acc[am][bn][2 * half], v1 = acc[am][bn][2 * half + 1];
                    if (rope) {
                        float c = cs[r * 64 + i], si = sn[r * 64 + i];
                        float t0 = v0 * c - v1 * si;
                        float t1 = v0 * si + v1 * c;
                        v0 = t0; v1 = t1;
                    }
                    uint32_t hb, lb;
                    pack_hl(v0, v1, hb, lb);
                    *(uint32_t*)&Oh[(size_t)r * ldc + col] = hb;
                    *(uint32_t*)&Ol[(size_t)r * ldc + col] = lb;
                }
            }
        }
    }
}

// ---------------- tensor-core flash attention (bf16x3, causal, GQA 4:1) ----------------
#define ATT_SMEM (192 * 1024)

__global__ __launch_bounds__(256, 1) void attn_mma(
    const __nv_bfloat16* __restrict__ qh_g, const __nv_bfloat16* __restrict__ ql_g,
    __nv_bfloat16* __restrict__ ah_g, __nv_bfloat16* __restrict__ al_g)
{
    extern __shared__ __align__(1024) char smb[];
    const uint32_t sb = smem_u32(smb);
    const uint32_t sQh = sb, sQl = sb + 32 * 1024;

    const int tid = threadIdx.x, lane = tid & 31, wid = tid >> 5;
    const int qt = (int)gridDim.x - 1 - (int)blockIdx.x;
    const int h = blockIdx.y, kvh = h >> 2;
    const int q0 = qt * 128;
    const int wq = wid * 16;

    #pragma unroll
    for (int i = 0; i < 8; i++) {
        int ch = tid + i * 256;
        int row = ch >> 4, c16 = ch & 15;
        uint32_t so = (uint32_t)(row * 256) + (uint32_t)((c16 ^ (row & 7)) << 4);
        size_t g = (size_t)(q0 + row) * QKV_N + h * HD + c16 * 8;
        cp16(sQh + so, qh_g + g);
        cp16(sQl + so, ql_g + g);
    }
    cp_commit();

    const int ktmax = 2 * qt + 1;
    auto load_kv = [&](int kt) {
        const uint32_t st = sb + 64 * 1024 + (uint32_t)(kt & 1) * 64 * 1024;
        const int k0 = kt * 64;
        #pragma unroll
        for (int i = 0; i < 4; i++) {
            int ch = tid + i * 256;
            int row = ch >> 4, c16 = ch & 15;
            uint32_t so = (uint32_t)(row * 256) + (uint32_t)((c16 ^ (row & 7)) << 4);
            size_t kb = (size_t)(k0 + row) * QKV_N + kvh * HD + c16 * 8;
            cp16(st + so,             qh_g + kb + K_OFF);
            cp16(st + 16 * 1024 + so, ql_g + kb + K_OFF);
            cp16(st + 32 * 1024 + so, qh_g + kb + V_OFF);
            cp16(st + 48 * 1024 + so, ql_g + kb + V_OFF);
        }
        cp_commit();
    };
    load_kv(0);

    float oacc[16][4];
    #pragma unroll
    for (int a = 0; a < 16; a++)
        #pragma unroll
        for (int q = 0; q < 4; q++) oacc[a][q] = 0.f;
    float m0 = -1e30f, m1 = -1e30f, l0 = 0.f, l1 = 0.f;
    const float kscale = 0.08838834764831845f * 1.44269504088896f;

    const int rin = lane & 7, grp = lane >> 3;
    const int arow = wq + rin + (grp & 1) * 8;
    const int r0 = lane >> 2;

    for (int kt = 0; kt <= ktmax; kt++) {
        if (kt < ktmax) { load_kv(kt + 1); cp_wait<1>(); }
        else            { cp_wait<0>(); }
        __syncthreads();

        const bool skip = (kt * 64) > (q0 + wq + 15);
        if (!skip) {
            const uint32_t st = sb + 64 * 1024 + (uint32_t)(kt & 1) * 64 * 1024;

            float sc[8][4];
            #pragma unroll
            for (int a = 0; a < 8; a++)
                #pragma unroll
                for (int q = 0; q < 4; q++) sc[a][q] = 0.f;

            #pragma unroll
            for (int k16 = 0; k16 < 8; k16++) {
                const int c16 = k16 * 2 + (grp >> 1);
                uint32_t aoff = (uint32_t)(arow * 256) + (uint32_t)((c16 ^ (arow & 7)) << 4);
                uint32_t aqh[4], aql[4];
                ldm_x4(aqh, sQh + aoff);
                ldm_x4(aql, sQl + aoff);
                #pragma unroll
                for (int bt = 0; bt < 4; bt++) {
                    int brow = bt * 16 + rin + (grp & 1) * 8;
                    uint32_t boff = (uint32_t)(brow * 256) + (uint32_t)((c16 ^ (brow & 7)) << 4);
                    uint32_t bh[4], bl[4];
                    ldm_x4(bh, st + boff);
                    ldm_x4(bl, st + 16 * 1024 + boff);
                    mma16816(sc[2 * bt],     aqh, bh[0], bh[2]);
                    mma16816(sc[2 * bt + 1], aqh, bh[1], bh[3]);
                    mma16816(sc[2 * bt],     aqh, bl[0], bl[2]);
                    mma16816(sc[2 * bt + 1], aqh, bl[1], bl[3]);
                    mma16816(sc[2 * bt],     aql, bh[0], bh[2]);
                    mma16816(sc[2 * bt + 1], aql, bh[1], bh[3]);
                }
            }

            if (kt * 64 + 63 > q0 + wq) {
                int qr0 = q0 + wq + r0, qr1 = qr0 + 8;
                int cb = kt * 64 + 2 * (lane & 3);
                #pragma unroll
                for (int a = 0; a < 8; a++) {
                    int c0 = cb + a * 8, c1 = c0 + 1;
                    if (c0 > qr0) sc[a][0] = -1e30f;
                    if (c1 > qr0) sc[a][1] = -1e30f;
                    if (c0 > qr1) sc[a][2] = -1e30f;
                    if (c1 > qr1) sc[a][3] = -1e30f;
                }
            }

            float mx0 = -1e30f, mx1 = -1e30f;
            #pragma unroll
            for (int a = 0; a < 8; a++) {
                mx0 = fmaxf(mx0, fmaxf(sc[a][0], sc[a][1]));
                mx1 = fmaxf(mx1, fmaxf(sc[a][2], sc[a][3]));
            }
            mx0 = fmaxf(mx0, __shfl_xor_sync(0xffffffffu, mx0, 1));
            mx0 = fmaxf(mx0, __shfl_xor_sync(0xffffffffu, mx0, 2));
            mx1 = fmaxf(mx1, __shfl_xor_sync(0xffffffffu, mx1, 1));
            mx1 = fmaxf(mx1, __shfl_xor_sync(0xffffffffu, mx1, 2));
            float nm0 = fmaxf(m0, mx0), nm1 = fmaxf(m1, mx1);
            float corr0 = exp2f((m0 - nm0) * kscale);
            float corr1 = exp2f((m1 - nm1) * kscale);
            float s0 = 0.f, s1 = 0.f;
            #pragma unroll
            for (int a = 0; a < 8; a++) {
                sc[a][0] = exp2f((sc[a][0] - nm0) * kscale);
                sc[a][1] = exp2f((sc[a][1] - nm0) * kscale);
                sc[a][2] = exp2f((sc[a][2] - nm1) * kscale);
                sc[a][3] = exp2f((sc[a][3] - nm1) * kscale);
                s0 += sc[a][0] + sc[a][1];
                s1 += sc[a][2] + sc[a][3];
            }
            s0 += __shfl_xor_sync(0xffffffffu, s0, 1);
            s0 += __shfl_xor_sync(0xffffffffu, s0, 2);
            s1 += __shfl_xor_sync(0xffffffffu, s1, 1);
            s1 += __shfl_xor_sync(0xffffffffu, s1, 2);
            l0 = l0 * corr0 + s0;
            l1 = l1 * corr1 + s1;
            m0 = nm0; m1 = nm1;
            #pragma unroll
            for (int a = 0; a < 16; a++) {
                oacc[a][0] *= corr0; oacc[a][1] *= corr0;
                oacc[a][2] *= corr1; oacc[a][3] *= corr1;
            }

            #pragma unroll
            for (int t = 0; t < 4; t++) {
                uint32_t ph[4], pl[4];
                pack_hl(sc[2 * t][0],     sc[2 * t][1],     ph[0], pl[0]);
                pack_hl(sc[2 * t][2],     sc[2 * t][3],     ph[1], pl[1]);
                pack_hl(sc[2 * t + 1][0], sc[2 * t + 1][1], ph[2], pl[2]);
                pack_hl(sc[2 * t + 1][2], sc[2 * t + 1][3], ph[3], pl[3]);
                #pragma unroll
                for (int d = 0; d < 8; d++) {
                    int vrow = t * 16 + (grp & 1) * 8 + rin;
                    int c16 = d * 2 + (grp >> 1);
                    uint32_t voff = (uint32_t)(vrow * 256) + (uint32_t)((c16 ^ (vrow & 7)) << 4);
                    uint32_t vh[4], vl[4];
                    ldm_x4t(vh, st + 32 * 1024 + voff);
                    ldm_x4t(vl, st + 48 * 1024 + voff);
                    mma16816(oacc[2 * d],     ph, vh[0], vh[1]);
                    mma16816(oacc[2 * d + 1], ph, vh[2], vh[3]);
                    mma16816(oacc[2 * d],     ph, vl[0], vl[1]);
                    mma16816(oacc[2 * d + 1], ph, vl[2], vl[3]);
                    mma16816(oacc[2 * d],     pl, vh[0], vh[1]);
                    mma16816(oacc[2 * d + 1], pl, vh[2], vh[3]);
                }
            }
        }
        __syncthreads();
    }

    float inv0 = 1.f / l0, inv1 = 1.f / l1;
    int gr0 = q0 + wq + r0, gr1 = gr0 + 8;
    #pragma unroll
    for (int a = 0; a < 16; a++) {
        int d0 = a * 8 + 2 * (lane & 3);
        float v0 = oacc[a][0] * inv0, v1 = oacc[a][1] * inv0;
        float w0 = oacc[a][2] * inv1, w1 = oacc[a][3] * inv1;
        uint32_t hb, lb;
        pack_hl(v0, v1, hb, lb);
        *(uint32_t*)&ah_g[(size_t)gr0 * DIM + h * HD + d0] = hb;
        *(uint32_t*)&al_g[(size_t)gr0 * DIM + h * HD + d0] = lb;
        pack_hl(w0, w1, hb, lb);
        *(uint32_t*)&ah_g[(size_t)gr1 * DIM + h * HD + d0] = hb;
        *(uint32_t*)&al_g[(size_t)gr1 * DIM + h * HD + d0] = lb;
    }
}

// ---------------- launch ----------------
extern "C" void kernel_launch(void* const* d_in, const int* in_sizes, int n_in,
                              void* d_out, int out_size)
{
    const float* x  = (const float*)d_in[0];
    const float* fc = (const float*)d_in[1];
    const float* fs = (const float*)d_in[2];
    const float* wq = (const float*)d_in[5];
    const float* wk = (const float*)d_in[6];
    const float* wv = (const float*)d_in[7];
    const float* wo = (const float*)d_in[8];
    float* out = (float*)d_out;

    __nv_bfloat16 *qh, *ql, *xh, *xl, *wh, *wl, *oh, *ol, *ah, *al;
    cudaGetSymbolAddress((void**)&qh, g_qh);  cudaGetSymbolAddress((void**)&ql, g_ql);
    cudaGetSymbolAddress((void**)&xh, g_xh);  cudaGetSymbolAddress((void**)&xl, g_xl);
    cudaGetSymbolAddress((void**)&wh, g_wh);  cudaGetSymbolAddress((void**)&wl, g_wl);
    cudaGetSymbolAddress((void**)&oh, g_oh);  cudaGetSymbolAddress((void**)&ol, g_ol);
    cudaGetSymbolAddress((void**)&ah, g_ah);  cudaGetSymbolAddress((void**)&al, g_al);

    cudaFuncSetAttribute(gemm_bf16x3, cudaFuncAttributeMaxDynamicSharedMemorySize, GEMM_SMEM);
    cudaFuncSetAttribute(attn_mma, cudaFuncAttributeMaxDynamicSharedMemorySize, ATT_SMEM);

    dim3 blk(256);
    int n4x = S * DIM / 4;
    split_kernel<<<(n4x + 255) / 256, blk>>>(x, xh, xl, n4x);
    int n4q = DIM * DIM / 4;
    split_kernel<<<(n4q + 255) / 256, blk>>>(wq, wh, wl, n4q);
    int n4k = 1024 * DIM / 4;
    split_kernel<<<(n4k + 255) / 256, blk>>>(wk, wh + (size_t)4096 * DIM, wl + (size_t)4096 * DIM, n4k);
    split_kernel<<<(n4k + 255) / 256, blk>>>(wv, wh + (size_t)5120 * DIM, wl + (size_t)5120 * DIM, n4k);
    split_kernel<<<(n4q + 255) / 256, blk>>>(wo, oh, ol, n4q);

    // QKV projection with fused RoPE + hi/lo split epilogue
    gemm_bf16x3<<<dim3(S / 128, QKV_N / 256), blk, GEMM_SMEM>>>(
        xh, xl, wh, wl, nullptr, DIM, QKV_N, 1, fc, fs, qh, ql);

    // tensor-core attention -> bf16 hi/lo output
    attn_mma<<<dim3(S / 128, NH), blk, ATT_SMEM>>>(qh, ql, ah, al);

    // output projection -> fp32 out
    gemm_bf16x3<<<dim3(S / 128, DIM / 256), blk, GEMM_SMEM>>>(
        ah, al, oh, ol, out, DIM, DIM, 0, nullptr, nullptr, nullptr, nullptr);
}